// round 8
// baseline (speedup 1.0000x reference)
#include <cuda_runtime.h>
#include <math.h>

#define DIMD 128
#define PMAX 3136

// Scratch: RECIPROCAL of diag(inv(b_covs[p]))[d], stored [D][P].
__device__ float g_rdinv[DIMD * PMAX];

// Fast reciprocal: rcp.approx + 1 Newton step (fp32-accurate).
__device__ __forceinline__ float frcp(float x) {
    float r; asm("rcp.approx.ftz.f32 %0, %1;" : "=f"(r) : "f"(x));
    return r * fmaf(-x, r, 2.0f);
}

__device__ __forceinline__ void ld4(float (&d)[4], const float* s) {
    float4 v = *reinterpret_cast<const float4*>(s);
    d[0]=v.x; d[1]=v.y; d[2]=v.z; d[3]=v.w;
}
__device__ __forceinline__ void ld8(float (&d)[8], const float* s) {
    const float4* s4 = reinterpret_cast<const float4*>(s);
    float4 v0 = s4[0], v1 = s4[1];
    d[0]=v0.x; d[1]=v0.y; d[2]=v0.z; d[3]=v0.w;
    d[4]=v1.x; d[5]=v1.y; d[6]=v1.z; d[7]=v1.w;
}

// ---------------------------------------------------------------------------
// Phase A: symmetric SWEEP on TWO patches packed into one 128x128 square:
//   Q[i][j] = A[i][j]            (i >= j)  patch A lower triangle + diagonal
//   Q[i][j] = B[j][i]            (i <  j)  patch B lower triangle, mirrored
//   diag(B) lives in straddle threads' dB[4] registers.
// After sweeping all k, each triangle = -inv(patch); emit -1/diag.
//
// Sweep step k (d = m_kk, rpv = 1/d):
//   m_ij' = m_ij - colv[i]*colv[j]*rpv     (i,j != k)
//   m_ik' = colv[i]*rpv ;  m_kj' = colv[j]*rpv ;  m_kk' = -rpv
// where colv[x] = M[max(x,k)][min(x,k)] (full column via symmetry).
//
// Tiling: 4x8 tiles on a 32x16 grid = 512 tiles = 512 threads.
//   - 480 "pure" tiles (fully below or above the diagonal): UNIFORM code,
//     only the staged-column pointer (colA vs colB) differs per thread.
//   - 32 "straddle" tiles (contain diagonal elements) map EXACTLY to warp 15
//     (tids 480..511): uniform mixed code, operand choice via selects.
// One staged column per patch per step (symmetry gives row AND column),
// double-buffered; ONE __syncthreads per step. All register-tile indices
// compile-time (templated KQ, unrolled a/b).
// ---------------------------------------------------------------------------

template<int BOFF>
__device__ __forceinline__ void upd_straddle(
    float (&T)[4][8], float (&dB)[4],
    const float (&ciA)[4], const float (&ciB)[4],
    const float (&sA)[8], const float (&sB)[8])
{
#pragma unroll
    for (int a = 0; a < 4; a++) {
#pragma unroll
        for (int b = 0; b < 8; b++) {
            if (b <= a + BOFF) T[a][b] = fmaf(-ciA[a], sA[b], T[a][b]);
            else               T[a][b] = fmaf(-ciB[a], sB[b], T[a][b]);
        }
        dB[a] = fmaf(-ciB[a], sB[a + BOFF], dB[a]);
    }
}

template<int KQ>
__device__ __forceinline__ void stage_pure(
    const float (&T)[4][8], float* dst,
    int r, int c, int kb2, int rb2, int R0, int C0)
{
    constexpr int AQ = KQ & 3;
    if (c == kb2) {
#pragma unroll
        for (int a = 0; a < 4; a++) dst[R0 + a] = T[a][KQ];
    } else if (r == rb2) {
#pragma unroll
        for (int b = 0; b < 8; b++) dst[C0 + b] = T[AQ][b];
    }
}

template<int KQ>
__device__ __forceinline__ void stage_straddle(
    const float (&T)[4][8], const float (&dB)[4],
    float* cAn, float* cBn,
    int r, int rb2, int R0, int C0, int k2)
{
    constexpr int AQ = KQ & 3;
    // column part (c == kb2 checked by caller)
#pragma unroll
    for (int a = 0; a < 4; a++) {
        int gi = R0 + a;
        if (gi > k2)      cAn[gi] = T[a][KQ];
        else if (gi < k2) cBn[gi] = T[a][KQ];
        else { cAn[gi] = T[a][KQ]; cBn[gi] = dB[a]; }
    }
    // row part (only the tile whose rows contain k2)
    if (r == rb2) {
#pragma unroll
        for (int b = 0; b < 8; b++) {
            int gj = C0 + b;
            if (gj < k2)      cAn[gj] = T[AQ][b];
            else if (gj > k2) cBn[gj] = T[AQ][b];
        }
    }
}

template<int KQ>
__device__ __forceinline__ void sweep_step(
    float (&T)[4][8], float (&dB)[4],
    float (&cA)[2][DIMD], float (&cB)[2][DIMD],
    int kb, bool straddle, bool low, int boff4,
    int r, int c, int R0, int C0)
{
    constexpr int BUF  = KQ & 1;
    constexpr int NBUF = BUF ^ 1;
    constexpr int AQ   = KQ & 3;
    const int k  = (kb << 3) + KQ;
    const int rb = k >> 2;

    if (!straddle) {
        const float* cX = low ? cA[BUF] : cB[BUF];
        float rpv = frcp(cX[k]);
        float ci[4], sj[8];
        ld4(ci, cX + R0);
        ld8(sj, cX + C0);
#pragma unroll
        for (int b = 0; b < 8; b++) sj[b] *= rpv;

#pragma unroll
        for (int a = 0; a < 4; a++)
#pragma unroll
            for (int b = 0; b < 8; b++)
                T[a][b] = fmaf(-ci[a], sj[b], T[a][b]);

        if (c == kb) {               // column-k fixup
#pragma unroll
            for (int a = 0; a < 4; a++) T[a][KQ] = ci[a] * rpv;
        }
        if (r == rb) {               // row-k fixup
#pragma unroll
            for (int b = 0; b < 8; b++) T[AQ][b] = sj[b];
        }

        const int k2 = k + 1;
        if (k2 < DIMD) {
            constexpr int KQ2 = (KQ + 1) & 7;
            stage_pure<KQ2>(T, low ? cA[NBUF] : cB[NBUF],
                            r, c, k2 >> 3, k2 >> 2, R0, C0);
        }
    } else {
        float rpvA = frcp(cA[BUF][k]);
        float rpvB = frcp(cB[BUF][k]);
        float ciA[4], ciB[4], sA[8], sB[8];
        ld4(ciA, &cA[BUF][R0]);
        ld4(ciB, &cB[BUF][R0]);
        ld8(sA, &cA[BUF][C0]);
        ld8(sB, &cB[BUF][C0]);
#pragma unroll
        for (int b = 0; b < 8; b++) { sA[b] *= rpvA; sB[b] *= rpvB; }

        // Branchless per-element operand select (boff4 is 0 or 4, uniform
        // per thread within the unrolled compare).
#pragma unroll
        for (int a = 0; a < 4; a++) {
#pragma unroll
            for (int b = 0; b < 8; b++) {
                bool useA = (b <= a + boff4);
                float u = useA ? ciA[a] : ciB[a];
                float v = useA ? sA[b]  : sB[b];
                T[a][b] = fmaf(-u, v, T[a][b]);
            }
            dB[a] = fmaf(-ciB[a], boff4 ? sB[a + 4] : sB[a], dB[a]);
        }

        if (r == rb) {               // row-k fixup (+ B diag)
#pragma unroll
            for (int b = 0; b < 8; b++) {
                int gj = C0 + b;
                T[AQ][b] = (gj < k) ? sA[b] : ((gj > k) ? sB[b] : -rpvA);
            }
            dB[AQ] = -rpvB;
        }
        if (c == kb) {               // column-k fixup
#pragma unroll
            for (int a = 0; a < 4; a++) {
                int gi = R0 + a;
                T[a][KQ] = (gi > k) ? (ciA[a] * rpvA)
                         : ((gi < k) ? (ciB[a] * rpvB) : -rpvA);
            }
        }

        const int k2 = k + 1;
        if (k2 < DIMD) {
            constexpr int KQ2 = (KQ + 1) & 7;
            if (c == (k2 >> 3))
                stage_straddle<KQ2>(T, dB, cA[NBUF], cB[NBUF],
                                    r, k2 >> 2, R0, C0, k2);
        }
    }
    __syncthreads();
}

__global__ __launch_bounds__(512, 1)
void sweep_diag_kernel(const float* __restrict__ covs, int P)
{
    int pA = blockIdx.x * 2;
    int pB = pA + 1;
    if (pB >= P) pB = pA;
    const float* MA = covs + (size_t)pA * DIMD * DIMD;
    const float* MB = covs + (size_t)pB * DIMD * DIMD;

    int tid = threadIdx.x;
    bool straddle = (tid >= 480);
    int r, c, boff4 = 0;
    bool low = true;
    if (straddle) {
        int j = tid - 480;
        r = j; c = j >> 1; boff4 = (j & 1) ? 4 : 0;
    } else {
        c = tid / 30;
        int i = tid - c * 30;
        if (i < 2 * c) { r = i; low = false; }   // upper (patch B)
        else           { r = i + 2; }            // lower (patch A)
    }
    int R0 = r << 2, C0 = c << 3;

    float T[4][8];
    float dB[4] = {0.f, 0.f, 0.f, 0.f};

    // ---------------- load tiles ----------------
    if (straddle) {
#pragma unroll
        for (int a = 0; a < 4; a++) {
#pragma unroll
            for (int b = 0; b < 8; b++) {
                bool isA = (b <= a + boff4);
                T[a][b] = isA ? MA[(size_t)(R0 + a) * DIMD + (C0 + b)]
                              : MB[(size_t)(C0 + b) * DIMD + (R0 + a)];
            }
            dB[a] = MB[(size_t)(R0 + a) * (DIMD + 1)];
        }
    } else if (low) {
#pragma unroll
        for (int a = 0; a < 4; a++) {
            const float4* src = reinterpret_cast<const float4*>(MA + (size_t)(R0 + a) * DIMD + C0);
            float4 v0 = src[0], v1 = src[1];
            T[a][0]=v0.x; T[a][1]=v0.y; T[a][2]=v0.z; T[a][3]=v0.w;
            T[a][4]=v1.x; T[a][5]=v1.y; T[a][6]=v1.z; T[a][7]=v1.w;
        }
    } else {
        // upper tile: T[a][b] = Q[R0+a][C0+b] = B[C0+b][R0+a]
#pragma unroll
        for (int b = 0; b < 8; b++) {
            float4 v = *reinterpret_cast<const float4*>(MB + (size_t)(C0 + b) * DIMD + R0);
            T[0][b]=v.x; T[1][b]=v.y; T[2][b]=v.z; T[3][b]=v.w;
        }
    }

    __shared__ __align__(16) float cA[2][DIMD];
    __shared__ __align__(16) float cB[2][DIMD];

    // Initial staging of column 0 for both patches (k2 = 0 -> buffer 0).
    if (straddle) {
        if (c == 0) stage_straddle<0>(T, dB, cA[0], cB[0], r, 0, R0, C0, 0);
    } else {
        stage_pure<0>(T, low ? cA[0] : cB[0], r, c, 0, 0, R0, C0);
    }
    __syncthreads();

#pragma unroll 1
    for (int kb = 0; kb < 16; kb++) {
        sweep_step<0>(T, dB, cA, cB, kb, straddle, low, boff4, r, c, R0, C0);
        sweep_step<1>(T, dB, cA, cB, kb, straddle, low, boff4, r, c, R0, C0);
        sweep_step<2>(T, dB, cA, cB, kb, straddle, low, boff4, r, c, R0, C0);
        sweep_step<3>(T, dB, cA, cB, kb, straddle, low, boff4, r, c, R0, C0);
        sweep_step<4>(T, dB, cA, cB, kb, straddle, low, boff4, r, c, R0, C0);
        sweep_step<5>(T, dB, cA, cB, kb, straddle, low, boff4, r, c, R0, C0);
        sweep_step<6>(T, dB, cA, cB, kb, straddle, low, boff4, r, c, R0, C0);
        sweep_step<7>(T, dB, cA, cB, kb, straddle, low, boff4, r, c, R0, C0);
    }

    // M = -inv(patch); emit rdinv = 1/diag(inv) = -1/T_diag.
    if (straddle) {
#pragma unroll
        for (int a = 0; a < 4; a++) {
            float vA = boff4 ? T[a][a + 4] : T[a][a];
            g_rdinv[(size_t)(R0 + a) * P + pA] = frcp(-vA);
            g_rdinv[(size_t)(R0 + a) * P + pB] = frcp(-dB[a]);
        }
    }
}

// ---------------------------------------------------------------------------
// Phase B: streaming whitening + cosine similarity.
// 4 lanes cooperate per (b,p) output (32 d's each) + shfl reduction.
// ---------------------------------------------------------------------------
__global__ void ace_kernel(const float* __restrict__ X,
                           const float* __restrict__ bmean,
                           const float* __restrict__ covs,
                           const float* __restrict__ sig,
                           const int* __restrict__ covtype,
                           float* __restrict__ out,
                           int B, int P)
{
    int gtid = blockIdx.x * blockDim.x + threadIdx.x;
    int idx  = gtid >> 2;
    int sub  = gtid & 3;
    if (idx >= B * P) return;
    int b = idx / P;
    int p = idx - b * P;
    int ct = *covtype;

    float ww = 0.f, ws = 0.f, ss = 0.f;

    if (ct == 0) {
        for (int m = sub * 32; m < sub * 32 + 32; m++) {
            float w = 0.f;
            const float* cr = covs + ((size_t)p * DIMD + m) * DIMD;
            for (int d = 0; d < DIMD; d++) {
                float xc = X[((size_t)b * DIMD + d) * P + p] - bmean[(size_t)d * P + p];
                w = fmaf(xc, cr[d], w);
            }
            float s = sig[(size_t)m * P + p];
            ww = fmaf(w, w, ww);
            ws = fmaf(w, s, ws);
            ss = fmaf(s, s, ss);
        }
    } else {
        bool use_diag = (ct == 1);
        int d0 = sub * 32;
#pragma unroll 16
        for (int i = 0; i < 32; i++) {
            int d = d0 + i;
            float xc = X[((size_t)b * DIMD + d) * P + p] - bmean[(size_t)d * P + p];
            float s  = sig[(size_t)d * P + p];
            float w  = use_diag ? (xc * g_rdinv[(size_t)d * P + p]) : xc;
            ww = fmaf(w, w, ww);
            ws = fmaf(w, s, ws);
            ss = fmaf(s, s, ss);
        }
    }

#pragma unroll
    for (int m = 1; m < 4; m <<= 1) {
        ww += __shfl_xor_sync(0xFFFFFFFF, ww, m);
        ws += __shfl_xor_sync(0xFFFFFFFF, ws, m);
        ss += __shfl_xor_sync(0xFFFFFFFF, ss, m);
    }

    if (sub == 0) {
        float denom = fmaxf(sqrtf(ww), 1e-12f) * fmaxf(sqrtf(ss), 1e-12f);
        out[idx] = ws / denom;
    }
}

extern "C" void kernel_launch(void* const* d_in, const int* in_sizes, int n_in,
                              void* d_out, int out_size)
{
    const float* X      = (const float*)d_in[0];
    const float* bmean  = (const float*)d_in[1];
    const float* covs   = (const float*)d_in[2];
    const float* sig    = (const float*)d_in[3];
    const int*   ctype  = (const int*)d_in[4];
    float*       out    = (float*)d_out;

    int P = in_sizes[2] / (DIMD * DIMD);           // 3136
    int B = in_sizes[0] / (DIMD * P);              // 32

    sweep_diag_kernel<<<(P + 1) / 2, 512>>>(covs, P);

    int total = B * P * 4;
    ace_kernel<<<(total + 255) / 256, 256>>>(X, bmean, covs, sig, ctype, out, B, P);
}

// round 9
// speedup vs baseline: 1.9539x; 1.9539x over previous
#include <cuda_runtime.h>
#include <math.h>

#define DIMD 128
#define PMAX 3136

// Scratch: RECIPROCAL of diag(inv(b_covs[p]))[d], stored [D][P].
__device__ float g_rdinv[DIMD * PMAX];

// Fast reciprocal: rcp.approx + 1 Newton step (fp32-accurate).
__device__ __forceinline__ float frcp(float x) {
    float r; asm("rcp.approx.ftz.f32 %0, %1;" : "=f"(r) : "f"(x));
    return r * fmaf(-x, r, 2.0f);
}

__device__ __forceinline__ void ld8(float (&d)[8], const float* s) {
    const float4* s4 = reinterpret_cast<const float4*>(s);
    float4 v0 = s4[0], v1 = s4[1];
    d[0]=v0.x; d[1]=v0.y; d[2]=v0.z; d[3]=v0.w;
    d[4]=v1.x; d[5]=v1.y; d[6]=v1.z; d[7]=v1.w;
}

// ---------------------------------------------------------------------------
// Phase A: symmetric SWEEP, TWO patches per CTA, R2's exact winning layout:
// 256 threads, 16x16 tile grid, 8x8 register tiles, occupancy 2.
//
//   Q[i][j] = A[i][j]   (i >= j) : patch A lower triangle + diagonal
//   Q[i][j] = B[j][i]   (i <  j) : patch B lower triangle, mirrored
//   diag(B) lives in DB[8] on the 16 diagonal-tile threads.
//
// Sweep step k (rpv = 1/m_kk):   m_ij' = m_ij - colv[i]*colv[j]*rpv,
//   m_ik' = colv[i]*rpv, m_kj' = colv[j]*rpv, m_kk' = -rpv.
// After all 128 steps each triangle holds -inv(patch); emit 1/(-diag).
//
// ONE staged column per patch per step (symmetry), double-buffered,
// ONE __syncthreads per step. Pure tiles run fully uniform code (only the
// column base pointer differs); the 16 diagonal tiles map to warp 7 so the
// two-path divergence is confined to one warp (~6% extra CTA issue).
// All register-tile indices are compile-time.
// ---------------------------------------------------------------------------
template<int KQ>
__device__ __forceinline__ void sweep_step(
    float (&T)[8][8], float (&DB)[8],
    float (&cA)[2][DIMD], float (&cB)[2][DIMD],
    int kk, bool isDiag, bool low, int ty, int tx, int R0, int C0)
{
    constexpr int BUF  = KQ & 1;
    constexpr int NBUF = BUF ^ 1;
    constexpr int KNQ  = (KQ + 1) & 7;
    const int k   = (kk << 3) + KQ;
    const int knb = kk + (KQ == 7 ? 1 : 0);     // block of column k+1

    if (!isDiag) {
        // ---------------- uniform pure-tile path ----------------
        const float* cX = low ? cA[BUF] : cB[BUF];
        float rpv = frcp(cX[k]);
        float ci[8], sj[8];
        ld8(ci, cX + R0);
        ld8(sj, cX + C0);
#pragma unroll
        for (int b = 0; b < 8; b++) sj[b] *= rpv;

#pragma unroll
        for (int a = 0; a < 8; a++)
#pragma unroll
            for (int b = 0; b < 8; b++)
                T[a][b] = fmaf(-ci[a], sj[b], T[a][b]);

        // Fixups (identical formulas for the A-role and mirrored B-role).
        if (ty == kk) {
#pragma unroll
            for (int b = 0; b < 8; b++) T[KQ][b] = sj[b];
        }
        if (tx == kk) {
#pragma unroll
            for (int a = 0; a < 8; a++) T[a][KQ] = ci[a] * rpv;
        }

        // Stage column k+1 of this thread's patch.
        if (k + 1 < DIMD) {
            float* dst = low ? cA[NBUF] : cB[NBUF];
            if (tx == knb) {
#pragma unroll
                for (int a = 0; a < 8; a++) dst[R0 + a] = T[a][KNQ];
            } else if (ty == knb) {
#pragma unroll
                for (int b = 0; b < 8; b++) dst[C0 + b] = T[KNQ][b];
            }
        }
    } else {
        // ---------------- diagonal-tile path (warp 7 only) ----------------
        float rpvA = frcp(cA[BUF][k]);
        float rpvB = frcp(cB[BUF][k]);
        float ciA[8], ciB[8], sjA[8], sjB[8];
        ld8(ciA, &cA[BUF][R0]);
        ld8(ciB, &cB[BUF][R0]);
#pragma unroll
        for (int x = 0; x < 8; x++) { sjA[x] = ciA[x] * rpvA; sjB[x] = ciB[x] * rpvB; }

#pragma unroll
        for (int a = 0; a < 8; a++) {
#pragma unroll
            for (int b = 0; b < 8; b++) {
                if (b <= a) T[a][b] = fmaf(-ciA[a], sjA[b], T[a][b]);   // A region
                else        T[a][b] = fmaf(-ciB[a], sjB[b], T[a][b]);   // B mirrored
            }
            DB[a] = fmaf(-ciB[a], sjB[a], DB[a]);                        // B diagonal
        }

        if (ty == kk) {     // pivot k is inside this tile's block
#pragma unroll
            for (int b = 0; b < 8; b++) {
                if (b < KQ)      T[KQ][b] = sjA[b];   // A row-k
                else if (b > KQ) T[KQ][b] = sjB[b];   // B col-k (mirrored)
            }
            T[KQ][KQ] = -rpvA;                        // A pivot
#pragma unroll
            for (int a = 0; a < 8; a++) {
                if (a > KQ)      T[a][KQ] = sjA[a];   // A col-k
                else if (a < KQ) T[a][KQ] = sjB[a];   // B row-k (mirrored)
            }
            DB[KQ] = -rpvB;                           // B pivot
        }

        // Stage column k+1 for BOTH patches (indices inside this block).
        if (k + 1 < DIMD && ty == knb) {
#pragma unroll
            for (int a = 0; a < 8; a++)
                cA[NBUF][R0 + a] = (a >= KNQ) ? T[a][KNQ] : T[KNQ][a];
#pragma unroll
            for (int x = 0; x < 8; x++)
                cB[NBUF][R0 + x] = (x > KNQ) ? T[KNQ][x]
                                 : ((x < KNQ) ? T[x][KNQ] : DB[KNQ]);
        }
    }
    __syncthreads();
}

__global__ __launch_bounds__(256, 2)
void sweep_diag_kernel(const float* __restrict__ covs, int P)
{
    int pA = blockIdx.x * 2;
    int pB = pA + 1;
    if (pB >= P) pB = pA;
    const float* MA = covs + (size_t)pA * DIMD * DIMD;
    const float* MB = covs + (size_t)pB * DIMD * DIMD;

    int tid = threadIdx.x;
    bool isDiag = (tid >= 224) && (tid < 240);
    int ty, tx;
    if (isDiag) {
        ty = tid - 224; tx = ty;              // all 16 diag tiles in warp 7
    } else {
        int s = (tid < 224) ? tid : (tid - 16);
        ty = s / 15;
        tx = s - ty * 15;
        tx += (tx >= ty) ? 1 : 0;             // skip the diagonal
    }
    bool low = (ty > tx);
    int R0 = ty << 3, C0 = tx << 3;

    float T[8][8];
    float DB[8];

    // ---------------- load tiles ----------------
    if (isDiag) {
#pragma unroll
        for (int a = 0; a < 8; a++) {
#pragma unroll
            for (int b = 0; b < 8; b++) {
                if (b <= a) T[a][b] = MA[(size_t)(R0 + a) * DIMD + (R0 + b)];
                else        T[a][b] = MB[(size_t)(R0 + b) * DIMD + (R0 + a)];
            }
            DB[a] = MB[(size_t)(R0 + a) * (DIMD + 1)];
        }
    } else if (low) {
#pragma unroll
        for (int a = 0; a < 8; a++) {
            const float4* src = reinterpret_cast<const float4*>(MA + (size_t)(R0 + a) * DIMD + C0);
            float4 v0 = src[0], v1 = src[1];
            T[a][0]=v0.x; T[a][1]=v0.y; T[a][2]=v0.z; T[a][3]=v0.w;
            T[a][4]=v1.x; T[a][5]=v1.y; T[a][6]=v1.z; T[a][7]=v1.w;
        }
#pragma unroll
        for (int a = 0; a < 8; a++) DB[a] = 0.0f;
    } else {
        // upper tile: T[a][b] = Q[R0+a][C0+b] = B[C0+b][R0+a]
#pragma unroll
        for (int b = 0; b < 8; b++) {
            const float4* src = reinterpret_cast<const float4*>(MB + (size_t)(C0 + b) * DIMD + R0);
            float4 v0 = src[0], v1 = src[1];
            T[0][b]=v0.x; T[1][b]=v0.y; T[2][b]=v0.z; T[3][b]=v0.w;
            T[4][b]=v1.x; T[5][b]=v1.y; T[6][b]=v1.z; T[7][b]=v1.w;
        }
#pragma unroll
        for (int a = 0; a < 8; a++) DB[a] = 0.0f;
    }

    __shared__ __align__(16) float cA[2][DIMD];
    __shared__ __align__(16) float cB[2][DIMD];

    // Initial staging of column 0 (knb = 0, KNQ = 0, into buffer 0).
    if (isDiag) {
        if (ty == 0) {
#pragma unroll
            for (int a = 0; a < 8; a++) cA[0][a] = T[a][0];
            cB[0][0] = DB[0];
#pragma unroll
            for (int x = 1; x < 8; x++) cB[0][x] = T[0][x];
        }
    } else {
        float* dst = low ? cA[0] : cB[0];
        if (tx == 0) {
#pragma unroll
            for (int a = 0; a < 8; a++) dst[R0 + a] = T[a][0];
        } else if (ty == 0) {
#pragma unroll
            for (int b = 0; b < 8; b++) dst[C0 + b] = T[0][b];
        }
    }
    __syncthreads();

#pragma unroll 1
    for (int kk = 0; kk < 16; kk++) {
        sweep_step<0>(T, DB, cA, cB, kk, isDiag, low, ty, tx, R0, C0);
        sweep_step<1>(T, DB, cA, cB, kk, isDiag, low, ty, tx, R0, C0);
        sweep_step<2>(T, DB, cA, cB, kk, isDiag, low, ty, tx, R0, C0);
        sweep_step<3>(T, DB, cA, cB, kk, isDiag, low, ty, tx, R0, C0);
        sweep_step<4>(T, DB, cA, cB, kk, isDiag, low, ty, tx, R0, C0);
        sweep_step<5>(T, DB, cA, cB, kk, isDiag, low, ty, tx, R0, C0);
        sweep_step<6>(T, DB, cA, cB, kk, isDiag, low, ty, tx, R0, C0);
        sweep_step<7>(T, DB, cA, cB, kk, isDiag, low, ty, tx, R0, C0);
    }

    // Triangles hold -inv(patch): rdinv = 1/diag(inv) = 1/(-T_diag).
    if (isDiag) {
#pragma unroll
        for (int a = 0; a < 8; a++) {
            g_rdinv[(size_t)(R0 + a) * P + pA] = frcp(-T[a][a]);
            g_rdinv[(size_t)(R0 + a) * P + pB] = frcp(-DB[a]);
        }
    }
}

// ---------------------------------------------------------------------------
// Phase B: streaming whitening + cosine similarity, COALESCED:
// block = 256 threads = 64 outputs x 4 d-quarters; a warp's 32 lanes read 32
// consecutive p => full 128B transactions. Cross-quarter reduction via smem.
// ---------------------------------------------------------------------------
__global__ void ace_kernel(const float* __restrict__ X,
                           const float* __restrict__ bmean,
                           const float* __restrict__ covs,
                           const float* __restrict__ sig,
                           const int* __restrict__ covtype,
                           float* __restrict__ out,
                           int B, int P)
{
    int t    = threadIdx.x;
    int sub  = t >> 6;                    // 0..3 : which quarter of D
    int slot = t & 63;                    // 0..63: output within block
    int idx  = blockIdx.x * 64 + slot;    // b*P + p
    bool valid = idx < B * P;
    int b = valid ? idx / P : 0;
    int p = valid ? idx - b * P : 0;
    int ct = *covtype;

    float ww = 0.f, ws = 0.f, ss = 0.f;

    if (valid) {
        if (ct == 0) {
            for (int m = sub * 32; m < sub * 32 + 32; m++) {
                float w = 0.f;
                const float* cr = covs + ((size_t)p * DIMD + m) * DIMD;
                for (int d = 0; d < DIMD; d++) {
                    float xc = X[((size_t)b * DIMD + d) * P + p] - bmean[(size_t)d * P + p];
                    w = fmaf(xc, cr[d], w);
                }
                float s = sig[(size_t)m * P + p];
                ww = fmaf(w, w, ww);
                ws = fmaf(w, s, ws);
                ss = fmaf(s, s, ss);
            }
        } else {
            bool use_diag = (ct == 1);
            int d0 = sub * 32;
#pragma unroll 16
            for (int i = 0; i < 32; i++) {
                int d = d0 + i;
                float xc = X[((size_t)b * DIMD + d) * P + p] - bmean[(size_t)d * P + p];
                float s  = sig[(size_t)d * P + p];
                float w  = use_diag ? (xc * g_rdinv[(size_t)d * P + p]) : xc;
                ww = fmaf(w, w, ww);
                ws = fmaf(w, s, ws);
                ss = fmaf(s, s, ss);
            }
        }
    }

    __shared__ float sred[3][4][64];
    sred[0][sub][slot] = ww;
    sred[1][sub][slot] = ws;
    sred[2][sub][slot] = ss;
    __syncthreads();

    if (sub == 0 && valid) {
        float tw = 0.f, ts = 0.f, tq = 0.f;
#pragma unroll
        for (int q = 0; q < 4; q++) {
            tw += sred[0][q][slot];
            ts += sred[1][q][slot];
            tq += sred[2][q][slot];
        }
        float denom = fmaxf(sqrtf(tw), 1e-12f) * fmaxf(sqrtf(tq), 1e-12f);
        out[idx] = ts / denom;
    }
}

extern "C" void kernel_launch(void* const* d_in, const int* in_sizes, int n_in,
                              void* d_out, int out_size)
{
    const float* X      = (const float*)d_in[0];
    const float* bmean  = (const float*)d_in[1];
    const float* covs   = (const float*)d_in[2];
    const float* sig    = (const float*)d_in[3];
    const int*   ctype  = (const int*)d_in[4];
    float*       out    = (float*)d_out;

    int P = in_sizes[2] / (DIMD * DIMD);           // 3136
    int B = in_sizes[0] / (DIMD * P);              // 32

    sweep_diag_kernel<<<(P + 1) / 2, 256>>>(covs, P);

    int total = B * P;
    ace_kernel<<<(total + 63) / 64, 256>>>(X, bmean, covs, sig, ctype, out, B, P);
}

// round 10
// speedup vs baseline: 2.0449x; 1.0466x over previous
#include <cuda_runtime.h>
#include <math.h>

#define DIMD 128
#define PMAX 3136

// Scratch: RECIPROCAL of diag(inv(b_covs[p]))[d], stored [D][P].
__device__ float g_rdinv[DIMD * PMAX];

// Fast reciprocal: rcp.approx + 1 Newton step (fp32-accurate).
__device__ __forceinline__ float frcp(float x) {
    float r; asm("rcp.approx.ftz.f32 %0, %1;" : "=f"(r) : "f"(x));
    return r * fmaf(-x, r, 2.0f);
}

__device__ __forceinline__ void ld8(float (&d)[8], const float* s) {
    const float4* s4 = reinterpret_cast<const float4*>(s);
    float4 v0 = s4[0], v1 = s4[1];
    d[0]=v0.x; d[1]=v0.y; d[2]=v0.z; d[3]=v0.w;
    d[4]=v1.x; d[5]=v1.y; d[6]=v1.z; d[7]=v1.w;
}

// ---------------------------------------------------------------------------
// Phase A: symmetric SWEEP, TWO patches per CTA (R9 algebra, verified), with
// a REGISTER-LIGHT diagonal path: patch A processed fully, then patch B,
// reusing one ci/sj register pair, so the max live set stays ~95 regs and
// ptxas cannot spill under __launch_bounds__(256,2). (R9's diag path kept
// 4 arrays live simultaneously -> ~130 regs -> spill -> 2x CTA-step cost.)
//
//   Q[i][j] = A[i][j]   (i >= j) : patch A lower triangle + diagonal
//   Q[i][j] = B[j][i]   (i <  j) : patch B lower triangle, mirrored
//   diag(B) in DB[8] on the 16 diagonal-tile threads (warp 7).
//
// Sweep step k (rpv = 1/m_kk):  m_ij' = m_ij - colv[i]*colv[j]*rpv,
//   m_ik' = colv[i]*rpv, m_kj' = colv[j]*rpv, m_kk' = -rpv.
// After 128 steps each triangle = -inv(patch); emit 1/(-diag).
// One staged column per patch per step, double-buffered, 1 barrier/step.
// ---------------------------------------------------------------------------
template<int KQ>
__device__ __forceinline__ void sweep_step(
    float (&T)[8][8], float (&DB)[8],
    float (&cA)[2][DIMD], float (&cB)[2][DIMD],
    int kk, bool isDiag, bool low, int ty, int tx, int R0, int C0)
{
    constexpr int BUF  = KQ & 1;
    constexpr int NBUF = BUF ^ 1;
    constexpr int KNQ  = (KQ + 1) & 7;
    const int k   = (kk << 3) + KQ;
    const int knb = kk + (KQ == 7 ? 1 : 0);     // block of column k+1

    if (!isDiag) {
        // ---------------- uniform pure-tile path ----------------
        const float* cX = low ? cA[BUF] : cB[BUF];
        float rpv = frcp(cX[k]);
        float ci[8], sj[8];
        ld8(ci, cX + R0);
        ld8(sj, cX + C0);
#pragma unroll
        for (int b = 0; b < 8; b++) sj[b] *= rpv;

#pragma unroll
        for (int a = 0; a < 8; a++)
#pragma unroll
            for (int b = 0; b < 8; b++)
                T[a][b] = fmaf(-ci[a], sj[b], T[a][b]);

        if (ty == kk) {
#pragma unroll
            for (int b = 0; b < 8; b++) T[KQ][b] = sj[b];
        }
        if (tx == kk) {
#pragma unroll
            for (int a = 0; a < 8; a++) T[a][KQ] = ci[a] * rpv;
        }

        if (k + 1 < DIMD) {
            float* dst = low ? cA[NBUF] : cB[NBUF];
            if (tx == knb) {
#pragma unroll
                for (int a = 0; a < 8; a++) dst[R0 + a] = T[a][KNQ];
            } else if (ty == knb) {
#pragma unroll
                for (int b = 0; b < 8; b++) dst[C0 + b] = T[KNQ][b];
            }
        }
    } else {
        // ------- diagonal-tile path (warp 7): A fully, THEN B (reg-light) ----
        {   // ---- patch A: region b <= a ----
            float rpv = frcp(cA[BUF][k]);
            float ci[8], sj[8];
            ld8(ci, &cA[BUF][R0]);          // C0 == R0 on diagonal tiles
#pragma unroll
            for (int x = 0; x < 8; x++) sj[x] = ci[x] * rpv;

#pragma unroll
            for (int a = 0; a < 8; a++)
#pragma unroll
                for (int b = 0; b <= a; b++)
                    T[a][b] = fmaf(-ci[a], sj[b], T[a][b]);

            if (ty == kk) {
#pragma unroll
                for (int b = 0; b < KQ; b++) T[KQ][b] = sj[b];   // A row-k
#pragma unroll
                for (int a = KQ + 1; a < 8; a++) T[a][KQ] = sj[a]; // A col-k
                T[KQ][KQ] = -rpv;                                  // A pivot
            }
        }
        {   // ---- patch B: region b > a (mirrored) + DB diagonal ----
            float rpv = frcp(cB[BUF][k]);
            float ci[8], sj[8];
            ld8(ci, &cB[BUF][R0]);
#pragma unroll
            for (int x = 0; x < 8; x++) sj[x] = ci[x] * rpv;

#pragma unroll
            for (int a = 0; a < 8; a++) {
#pragma unroll
                for (int b = a + 1; b < 8; b++)
                    T[a][b] = fmaf(-ci[b], sj[a], T[a][b]);   // B[gj][gi]
                DB[a] = fmaf(-ci[a], sj[a], DB[a]);
            }

            if (ty == kk) {
#pragma unroll
                for (int b = KQ + 1; b < 8; b++) T[KQ][b] = sj[b]; // B col-k
#pragma unroll
                for (int a = 0; a < KQ; a++) T[a][KQ] = sj[a];     // B row-k
                DB[KQ] = -rpv;                                     // B pivot
            }
        }

        // Stage column k+1 for BOTH patches (pivot block entries only).
        if (k + 1 < DIMD && ty == knb) {
#pragma unroll
            for (int a = 0; a < 8; a++)
                cA[NBUF][R0 + a] = (a >= KNQ) ? T[a][KNQ] : T[KNQ][a];
#pragma unroll
            for (int x = 0; x < 8; x++)
                cB[NBUF][R0 + x] = (x > KNQ) ? T[KNQ][x]
                                 : ((x < KNQ) ? T[x][KNQ] : DB[KNQ]);
        }
    }
    __syncthreads();
}

__global__ __launch_bounds__(256, 2)
void sweep_diag_kernel(const float* __restrict__ covs, int P)
{
    int pA = blockIdx.x * 2;
    int pB = pA + 1;
    if (pB >= P) pB = pA;
    const float* MA = covs + (size_t)pA * DIMD * DIMD;
    const float* MB = covs + (size_t)pB * DIMD * DIMD;

    int tid = threadIdx.x;
    bool isDiag = (tid >= 224) && (tid < 240);
    int ty, tx;
    if (isDiag) {
        ty = tid - 224; tx = ty;              // all 16 diag tiles in warp 7
    } else {
        int s = (tid < 224) ? tid : (tid - 16);
        ty = s / 15;
        tx = s - ty * 15;
        tx += (tx >= ty) ? 1 : 0;             // skip the diagonal
    }
    bool low = (ty > tx);
    int R0 = ty << 3, C0 = tx << 3;

    float T[8][8];
    float DB[8];

    // ---------------- load tiles ----------------
    if (isDiag) {
#pragma unroll
        for (int a = 0; a < 8; a++) {
#pragma unroll
            for (int b = 0; b < 8; b++) {
                if (b <= a) T[a][b] = MA[(size_t)(R0 + a) * DIMD + (R0 + b)];
                else        T[a][b] = MB[(size_t)(R0 + b) * DIMD + (R0 + a)];
            }
            DB[a] = MB[(size_t)(R0 + a) * (DIMD + 1)];
        }
    } else if (low) {
#pragma unroll
        for (int a = 0; a < 8; a++) {
            const float4* src = reinterpret_cast<const float4*>(MA + (size_t)(R0 + a) * DIMD + C0);
            float4 v0 = src[0], v1 = src[1];
            T[a][0]=v0.x; T[a][1]=v0.y; T[a][2]=v0.z; T[a][3]=v0.w;
            T[a][4]=v1.x; T[a][5]=v1.y; T[a][6]=v1.z; T[a][7]=v1.w;
        }
#pragma unroll
        for (int a = 0; a < 8; a++) DB[a] = 0.0f;
    } else {
        // upper tile: T[a][b] = Q[R0+a][C0+b] = B[C0+b][R0+a]
#pragma unroll
        for (int b = 0; b < 8; b++) {
            const float4* src = reinterpret_cast<const float4*>(MB + (size_t)(C0 + b) * DIMD + R0);
            float4 v0 = src[0], v1 = src[1];
            T[0][b]=v0.x; T[1][b]=v0.y; T[2][b]=v0.z; T[3][b]=v0.w;
            T[4][b]=v1.x; T[5][b]=v1.y; T[6][b]=v1.z; T[7][b]=v1.w;
        }
#pragma unroll
        for (int a = 0; a < 8; a++) DB[a] = 0.0f;
    }

    __shared__ __align__(16) float cA[2][DIMD];
    __shared__ __align__(16) float cB[2][DIMD];

    // Initial staging of column 0 (block 0, KNQ = 0, buffer 0).
    if (isDiag) {
        if (ty == 0) {
#pragma unroll
            for (int a = 0; a < 8; a++) cA[0][a] = T[a][0];
            cB[0][0] = DB[0];
#pragma unroll
            for (int x = 1; x < 8; x++) cB[0][x] = T[0][x];
        }
    } else {
        float* dst = low ? cA[0] : cB[0];
        if (tx == 0) {
#pragma unroll
            for (int a = 0; a < 8; a++) dst[R0 + a] = T[a][0];
        } else if (ty == 0) {
#pragma unroll
            for (int b = 0; b < 8; b++) dst[C0 + b] = T[0][b];
        }
    }
    __syncthreads();

#pragma unroll 1
    for (int kk = 0; kk < 16; kk++) {
        sweep_step<0>(T, DB, cA, cB, kk, isDiag, low, ty, tx, R0, C0);
        sweep_step<1>(T, DB, cA, cB, kk, isDiag, low, ty, tx, R0, C0);
        sweep_step<2>(T, DB, cA, cB, kk, isDiag, low, ty, tx, R0, C0);
        sweep_step<3>(T, DB, cA, cB, kk, isDiag, low, ty, tx, R0, C0);
        sweep_step<4>(T, DB, cA, cB, kk, isDiag, low, ty, tx, R0, C0);
        sweep_step<5>(T, DB, cA, cB, kk, isDiag, low, ty, tx, R0, C0);
        sweep_step<6>(T, DB, cA, cB, kk, isDiag, low, ty, tx, R0, C0);
        sweep_step<7>(T, DB, cA, cB, kk, isDiag, low, ty, tx, R0, C0);
    }

    // Triangles hold -inv(patch): rdinv = 1/diag(inv) = 1/(-T_diag).
    if (isDiag) {
#pragma unroll
        for (int a = 0; a < 8; a++) {
            g_rdinv[(size_t)(R0 + a) * P + pA] = frcp(-T[a][a]);
            g_rdinv[(size_t)(R0 + a) * P + pB] = frcp(-DB[a]);
        }
    }
}

// ---------------------------------------------------------------------------
// Phase B: streaming whitening + cosine similarity, coalesced:
// block = 256 threads = 64 outputs x 4 d-quarters; a warp's 32 lanes read 32
// consecutive p => full 128B transactions. Cross-quarter reduction via smem.
// ---------------------------------------------------------------------------
__global__ void ace_kernel(const float* __restrict__ X,
                           const float* __restrict__ bmean,
                           const float* __restrict__ covs,
                           const float* __restrict__ sig,
                           const int* __restrict__ covtype,
                           float* __restrict__ out,
                           int B, int P)
{
    int t    = threadIdx.x;
    int sub  = t >> 6;                    // 0..3 : which quarter of D
    int slot = t & 63;                    // 0..63: output within block
    int idx  = blockIdx.x * 64 + slot;    // b*P + p
    bool valid = idx < B * P;
    int b = valid ? idx / P : 0;
    int p = valid ? idx - b * P : 0;
    int ct = *covtype;

    float ww = 0.f, ws = 0.f, ss = 0.f;

    if (valid) {
        if (ct == 0) {
            for (int m = sub * 32; m < sub * 32 + 32; m++) {
                float w = 0.f;
                const float* cr = covs + ((size_t)p * DIMD + m) * DIMD;
                for (int d = 0; d < DIMD; d++) {
                    float xc = X[((size_t)b * DIMD + d) * P + p] - bmean[(size_t)d * P + p];
                    w = fmaf(xc, cr[d], w);
                }
                float s = sig[(size_t)m * P + p];
                ww = fmaf(w, w, ww);
                ws = fmaf(w, s, ws);
                ss = fmaf(s, s, ss);
            }
        } else {
            bool use_diag = (ct == 1);
            int d0 = sub * 32;
#pragma unroll 16
            for (int i = 0; i < 32; i++) {
                int d = d0 + i;
                float xc = X[((size_t)b * DIMD + d) * P + p] - bmean[(size_t)d * P + p];
                float s  = sig[(size_t)d * P + p];
                float w  = use_diag ? (xc * g_rdinv[(size_t)d * P + p]) : xc;
                ww = fmaf(w, w, ww);
                ws = fmaf(w, s, ws);
                ss = fmaf(s, s, ss);
            }
        }
    }

    __shared__ float sred[3][4][64];
    sred[0][sub][slot] = ww;
    sred[1][sub][slot] = ws;
    sred[2][sub][slot] = ss;
    __syncthreads();

    if (sub == 0 && valid) {
        float tw = 0.f, ts = 0.f, tq = 0.f;
#pragma unroll
        for (int q = 0; q < 4; q++) {
            tw += sred[0][q][slot];
            ts += sred[1][q][slot];
            tq += sred[2][q][slot];
        }
        float denom = fmaxf(sqrtf(tw), 1e-12f) * fmaxf(sqrtf(tq), 1e-12f);
        out[idx] = ts / denom;
    }
}

extern "C" void kernel_launch(void* const* d_in, const int* in_sizes, int n_in,
                              void* d_out, int out_size)
{
    const float* X      = (const float*)d_in[0];
    const float* bmean  = (const float*)d_in[1];
    const float* covs   = (const float*)d_in[2];
    const float* sig    = (const float*)d_in[3];
    const int*   ctype  = (const int*)d_in[4];
    float*       out    = (float*)d_out;

    int P = in_sizes[2] / (DIMD * DIMD);           // 3136
    int B = in_sizes[0] / (DIMD * P);              // 32

    sweep_diag_kernel<<<(P + 1) / 2, 256>>>(covs, P);

    int total = B * P;
    ace_kernel<<<(total + 63) / 64, 256>>>(X, bmean, covs, sig, ctype, out, B, P);
}